// round 1
// baseline (speedup 1.0000x reference)
#include <cuda_runtime.h>
#include <math.h>

#define HH 128
#define WW 128
#define HW 16384
#define NIMG 20
#define CHUNK 4

// ---------------- scratch (device globals; no allocation allowed) ----------------
__device__ float g_bufA[(size_t)NIMG * 64 * HW];
__device__ float g_bufB[(size_t)NIMG * 64 * HW];
__device__ float g_bufT[(size_t)NIMG * 64 * HW];
__device__ float g_cat [(size_t)NIMG * 128 * HW];   // also reused as the "o" buffer
__device__ float g_om  [(size_t)NIMG * 216 * HW];
__device__ float g_col [(size_t)NIMG * 576 * HW];

// ---------------- generic 3x3 SAME conv (cross-correlation) ----------------
// Block: 256 threads. Output tile: 16 rows x 64 cols x 16 out-channels.
// Thread: tx = tid&15 -> cols {tx, tx+16, tx+32, tx+48}; ty = tid>>4 -> row.
// Loops input channels in chunks of 4 staged through smem.
__global__ __launch_bounds__(256, 2) void conv3x3_kernel(
    const float* __restrict__ in, const float* __restrict__ wt,
    const float* __restrict__ bias, float* __restrict__ out,
    const float* __restrict__ addsrc,
    int Cin, int Cout, int doRelu)
{
    __shared__ __align__(16) float sIn[CHUNK][18][80];   // rows 18, cols 66 used (stride 80: bank-conflict-free)
    __shared__ __align__(16) float sW[CHUNK][9][16];

    const int tw  = blockIdx.x & 1;        // W tile (64 wide)
    const int th  = blockIdx.x >> 1;       // H tile (16 tall)
    const int img = blockIdx.y;
    const int cob = blockIdx.z * 16;
    const int tid = threadIdx.x;
    const int tx  = tid & 15;
    const int ty  = tid >> 4;

    float acc[4][16];
#pragma unroll
    for (int p = 0; p < 4; p++)
#pragma unroll
        for (int c = 0; c < 16; c++) acc[p][c] = 0.f;

    const int nch = (Cin + CHUNK - 1) / CHUNK;
    for (int cc = 0; cc < nch; cc++) {
        const int cin0 = cc * CHUNK;
        // ---- load input tile (with SAME zero padding) ----
        for (int idx = tid; idx < CHUNK * 18 * 66; idx += 256) {
            int ci  = idx / (18 * 66);
            int rem = idx - ci * (18 * 66);
            int r = rem / 66, c = rem - r * 66;
            int gr = th * 16 + r - 1;
            int gc = tw * 64 + c - 1;
            int cin = cin0 + ci;
            float v = 0.f;
            if (cin < Cin && gr >= 0 && gr < HH && gc >= 0 && gc < WW)
                v = in[((size_t)img * Cin + cin) * HW + gr * WW + gc];
            sIn[ci][r][c] = v;
        }
        // ---- load weights chunk: sW[ci][k][co] ----
        for (int idx = tid; idx < CHUNK * 9 * 16; idx += 256) {
            int ci  = idx / 144;
            int rem = idx - ci * 144;
            int k = rem >> 4, co = rem & 15;
            int cin = cin0 + ci;
            float v = 0.f;
            if (cin < Cin && (cob + co) < Cout)
                v = wt[((size_t)(cob + co) * Cin + cin) * 9 + k];
            sW[ci][k][co] = v;
        }
        __syncthreads();

        for (int ci = 0; ci < CHUNK; ci++) {
#pragma unroll
            for (int k = 0; k < 9; k++) {
                const int ky = k / 3, kx = k - ky * 3;
                const float4 w0 = *(const float4*)&sW[ci][k][0];
                const float4 w1 = *(const float4*)&sW[ci][k][4];
                const float4 w2 = *(const float4*)&sW[ci][k][8];
                const float4 w3 = *(const float4*)&sW[ci][k][12];
                const float wv[16] = {w0.x, w0.y, w0.z, w0.w, w1.x, w1.y, w1.z, w1.w,
                                      w2.x, w2.y, w2.z, w2.w, w3.x, w3.y, w3.z, w3.w};
#pragma unroll
                for (int p = 0; p < 4; p++) {
                    const float xv = sIn[ci][ty + ky][tx + 16 * p + kx];
#pragma unroll
                    for (int co = 0; co < 16; co++)
                        acc[p][co] = fmaf(xv, wv[co], acc[p][co]);
                }
            }
        }
        __syncthreads();
    }

    // ---- epilogue ----
    const int row = th * 16 + ty;
    const int colb = tw * 64 + tx;
#pragma unroll
    for (int co = 0; co < 16; co++) {
        const int oc = cob + co;
        if (oc < Cout) {
            const float b = bias[oc];
#pragma unroll
            for (int p = 0; p < 4; p++) {
                const size_t idx = ((size_t)img * Cout + oc) * HW + row * WW + colb + 16 * p;
                float v = acc[p][co] + b;
                if (addsrc) v += addsrc[idx];
                if (doRelu) v = fmaxf(v, 0.f);
                out[idx] = v;
            }
        }
    }
}

// ---------------- pack [ref | nei] concat buffer ----------------
__global__ void pack_cat_kernel(const float* __restrict__ feat, float* __restrict__ cat)
{
    const int gid = blockIdx.x * 256 + threadIdx.x;   // total 20*128*HW
    const int px = gid & (HW - 1);
    const int t  = gid >> 14;
    const int ch = t & 127;
    const int j  = t >> 7;
    const int b  = j / 5;
    float v;
    if (ch < 64) v = feat[((size_t)(b * 5 + 2) * 64 + ch) * HW + px];
    else         v = feat[((size_t)j * 64 + (ch - 64)) * HW + px];
    cat[gid] = v;
}

// ---------------- modulated deformable im2col (DCNv2) ----------------
// One thread per (j, g, k, pixel); computes 8 channels of its group.
// col layout: col[j][(g*8+c)*9 + k][px]  (standard cin*9+k ordering)
__global__ void dcn_im2col_kernel(const float* __restrict__ x,
                                  const float* __restrict__ om,
                                  float* __restrict__ col)
{
    const int gid = blockIdx.x * 256 + threadIdx.x;   // total 20*72*HW
    const int px = gid & (HW - 1);
    const int t  = gid >> 14;      // j*72 + g*9 + k
    const int gk = t % 72;
    const int j  = t / 72;
    const int g  = gk / 9, k = gk - g * 9;
    const int h  = px >> 7, w = px & 127;

    const float* omj = om + (size_t)j * 216 * HW;
    const float dy = omj[(size_t)(gk)       * HW + px];
    const float dx = omj[(size_t)(72  + gk) * HW + px];
    float m        = omj[(size_t)(144 + gk) * HW + px];
    m = 1.f / (1.f + expf(-m));

    const float py  = (float)h + (float)(k / 3 - 1) + dy;
    const float pxf = (float)w + (float)(k % 3 - 1) + dx;
    const float y0f = floorf(py), x0f = floorf(pxf);
    const float wy = py - y0f, wx = pxf - x0f;
    const int y0 = (int)y0f, x0 = (int)x0f;
    const int y1 = y0 + 1,   x1 = x0 + 1;
    const bool vy0 = (y0 >= 0) & (y0 < HH), vy1 = (y1 >= 0) & (y1 < HH);
    const bool vx0 = (x0 >= 0) & (x0 < WW), vx1 = (x1 >= 0) & (x1 < WW);
    const int cy0 = min(max(y0, 0), HH - 1), cy1 = min(max(y1, 0), HH - 1);
    const int cx0 = min(max(x0, 0), WW - 1), cx1 = min(max(x1, 0), WW - 1);
    const float w00 = (1.f - wy) * (1.f - wx) * m * ((vy0 && vx0) ? 1.f : 0.f);
    const float w01 = (1.f - wy) * wx         * m * ((vy0 && vx1) ? 1.f : 0.f);
    const float w10 = wy * (1.f - wx)         * m * ((vy1 && vx0) ? 1.f : 0.f);
    const float w11 = wy * wx                 * m * ((vy1 && vx1) ? 1.f : 0.f);

    const int i00 = cy0 * WW + cx0, i01 = cy0 * WW + cx1;
    const int i10 = cy1 * WW + cx0, i11 = cy1 * WW + cx1;

    const float* xg = x + ((size_t)j * 64 + g * 8) * HW;
    const size_t colbase = ((size_t)j * 576 + (size_t)(g * 8) * 9 + k) * HW + px;
#pragma unroll
    for (int c = 0; c < 8; c++) {
        const float* xc = xg + (size_t)c * HW;
        const float v = w00 * xc[i00] + w01 * xc[i01] + w10 * xc[i10] + w11 * xc[i11];
        col[colbase + (size_t)c * 9 * HW] = v;
    }
}

// ---------------- GEMM over col buffer: out[o,px] = W[o,:] @ col[:,px] + b ----------------
// Tile: 32 co x 128 px; thread: 4 co x 4 px (float4 both sides).
__global__ __launch_bounds__(256) void gemm_col_kernel(
    const float* __restrict__ wt,   // [Cout][Kdim]
    const float* __restrict__ colb, // [img][Kdim][HW]
    const float* __restrict__ bias,
    float* __restrict__ out,        // [img][Cout][HW]
    int Kdim, int Cout)
{
    __shared__ __align__(16) float sC[16][128];
    __shared__ __align__(16) float sW[16][32];

    const int pxb = blockIdx.x * 128;
    const int img = blockIdx.y;
    const int cob = blockIdx.z * 32;
    const int tid = threadIdx.x;
    const int tx = tid & 31;
    const int ty = tid >> 5;

    float acc[4][4] = {};   // [co][px]

    for (int k0 = 0; k0 < Kdim; k0 += 16) {
        for (int i = tid; i < 512; i += 256) {
            const int kk = i >> 5, c4 = i & 31;
            *(float4*)&sC[kk][c4 * 4] =
                *(const float4*)&colb[((size_t)img * Kdim + k0 + kk) * HW + pxb + c4 * 4];
        }
        for (int i = tid; i < 512; i += 256) {
            const int kk = i >> 5, co = i & 31;
            sW[kk][co] = wt[(size_t)(cob + co) * Kdim + k0 + kk];
        }
        __syncthreads();
#pragma unroll
        for (int kk = 0; kk < 16; kk++) {
            const float4 xv = *(const float4*)&sC[kk][tx * 4];
            const float4 wv = *(const float4*)&sW[kk][ty * 4];
            const float xs[4] = {xv.x, xv.y, xv.z, xv.w};
            const float ws[4] = {wv.x, wv.y, wv.z, wv.w};
#pragma unroll
            for (int c = 0; c < 4; c++)
#pragma unroll
                for (int p = 0; p < 4; p++)
                    acc[c][p] = fmaf(ws[c], xs[p], acc[c][p]);
        }
        __syncthreads();
    }

#pragma unroll
    for (int c = 0; c < 4; c++) {
        const int oc = cob + ty * 4 + c;
        const float b = bias[oc];
        float4 v = make_float4(acc[c][0] + b, acc[c][1] + b, acc[c][2] + b, acc[c][3] + b);
        *(float4*)&out[((size_t)img * Cout + oc) * HW + pxb + tx * 4] = v;
    }
}

// ---------------- host launcher ----------------
static inline void launch_conv(const float* in, const float* w, const float* b,
                               float* out, const float* add,
                               int Cin, int Cout, int relu)
{
    dim3 grid(16, NIMG, (Cout + 15) / 16);
    conv3x3_kernel<<<grid, 256>>>(in, w, b, out, add, Cin, Cout, relu);
}

extern "C" void kernel_launch(void* const* d_in, const int* in_sizes, int n_in,
                              void* d_out, int out_size)
{
    const float* x       = (const float*)d_in[0];
    const float* w_init  = (const float*)d_in[1];
    const float* b_init  = (const float*)d_in[2];
    const float* res_w1  = (const float*)d_in[3];
    const float* res_b1  = (const float*)d_in[4];
    const float* res_w2  = (const float*)d_in[5];
    const float* res_b2  = (const float*)d_in[6];
    const float* w_bn    = (const float*)d_in[7];
    const float* b_bn    = (const float*)d_in[8];
    const float* off_w   = (const float*)d_in[9];
    const float* off_b   = (const float*)d_in[10];
    const float* com_w   = (const float*)d_in[11];
    const float* com_b   = (const float*)d_in[12];
    const float* dcn_w   = (const float*)d_in[13];
    const float* dcn_b   = (const float*)d_in[14];
    const float* w_rec   = (const float*)d_in[15];
    const float* b_rec   = (const float*)d_in[16];
    float* out = (float*)d_out;

    float *bufA, *bufB, *bufT, *cat, *om, *colb;
    cudaGetSymbolAddress((void**)&bufA, g_bufA);
    cudaGetSymbolAddress((void**)&bufB, g_bufB);
    cudaGetSymbolAddress((void**)&bufT, g_bufT);
    cudaGetSymbolAddress((void**)&cat,  g_cat);
    cudaGetSymbolAddress((void**)&om,   g_om);
    cudaGetSymbolAddress((void**)&colb, g_col);
    float* obuf = cat;   // reuse cat region as the "o" buffer after cat is consumed

    // 1) init conv + relu  (x viewed as [20,1,128,128])
    launch_conv(x, w_init, b_init, bufA, nullptr, 1, 64, 1);

    // 2) 5 residual blocks (ping-pong A <-> B)
    float* cur = bufA;
    float* nxt = bufB;
    for (int i = 0; i < 5; i++) {
        launch_conv(cur, res_w1 + (size_t)i * 64 * 64 * 9, res_b1 + i * 64, bufT, nullptr, 64, 64, 1);
        launch_conv(bufT, res_w2 + (size_t)i * 64 * 64 * 9, res_b2 + i * 64, nxt, cur, 64, 64, 0);
        float* t = cur; cur = nxt; nxt = t;
    }
    float* feat = cur;   // = bufB after 5 iterations; preserved below

    // 3) pack [ref | nei] and bottleneck conv (Cin=128)
    pack_cat_kernel<<<(NIMG * 128 * HW) / 256, 256>>>(feat, cat);
    launch_conv(cat, w_bn, b_bn, bufA, nullptr, 128, 64, 0);

    // 4) four chained DCN stages
    dim3 ggemm(HW / 128, NIMG, 2);
    const int im2colBlocks = (NIMG * 72 * HW) / 256;

    auto dcn_stage = [&](const float* xsrc, const float* feaSrc, int di, float* outBuf) {
        launch_conv(feaSrc, off_w + (size_t)di * 64 * 64 * 9, off_b + di * 64, obuf, nullptr, 64, 64, 0);
        launch_conv(obuf, com_w + (size_t)di * 216 * 64 * 9, com_b + di * 216, om, nullptr, 64, 216, 0);
        dcn_im2col_kernel<<<im2colBlocks, 256>>>(xsrc, om, colb);
        gemm_col_kernel<<<ggemm, 256>>>(dcn_w + (size_t)di * 64 * 64 * 9, colb,
                                        dcn_b + di * 64, outBuf, 576, 64);
    };

    dcn_stage(bufA, bufA, 0, bufT);   // fea = dcn(fea, o0)
    dcn_stage(bufT, bufT, 1, bufA);   // fea = dcn(fea, o1)
    dcn_stage(feat, bufA, 2, bufT);   // fea = dcn(nei, o2)   (x = nei!)
    dcn_stage(bufT, bufT, 3, bufA);   // aligned = dcn(fea, o3)

    // 5) reconstruction conv (Cout=1) straight into d_out: layout [b,n,H,W] == [j,H,W]
    launch_conv(bufA, w_rec, b_rec, out, nullptr, 64, 1, 0);
}

// round 2
// speedup vs baseline: 1.7850x; 1.7850x over previous
#include <cuda_runtime.h>
#include <math.h>

#define HH 128
#define WW 128
#define HW 16384
#define NIMG 20
#define CHUNK 4
#define SIN_CI 396   // per-ci smem stride for conv input tile (396 % 32 == 12 -> conflict-free B frags)

// ---------------- scratch (device globals; no allocation allowed) ----------------
__device__ float g_bufA[(size_t)NIMG * 64 * HW];
__device__ float g_bufB[(size_t)NIMG * 64 * HW];
__device__ float g_bufT[(size_t)NIMG * 64 * HW];
__device__ float g_cat [(size_t)NIMG * 128 * HW];   // also reused as the "o" buffer
__device__ float g_om  [(size_t)NIMG * 216 * HW];
__device__ float g_col [(size_t)NIMG * 576 * HW];

// ---------------- tf32 helpers ----------------
__device__ __forceinline__ float to_tf32(float v) {
    unsigned u;
    asm("cvt.rna.tf32.f32 %0, %1;" : "=r"(u) : "f"(v));
    return __uint_as_float(u);
}

__device__ __forceinline__ void mma_tf32(float* c, const float* a, const float* b) {
    asm volatile(
        "mma.sync.aligned.m16n8k8.row.col.f32.tf32.tf32.f32 "
        "{%0,%1,%2,%3}, {%4,%5,%6,%7}, {%8,%9}, {%0,%1,%2,%3};"
        : "+f"(c[0]), "+f"(c[1]), "+f"(c[2]), "+f"(c[3])
        : "r"(__float_as_uint(a[0])), "r"(__float_as_uint(a[1])),
          "r"(__float_as_uint(a[2])), "r"(__float_as_uint(a[3])),
          "r"(__float_as_uint(b[0])), "r"(__float_as_uint(b[1])));
}

// ---------------- tf32 implicit-GEMM 3x3 SAME conv ----------------
// Block: 256 thr = 8 warps (2 M x 4 N). Tile: 64 Cout x 128 px (one image row).
// K order: tap k outer (9), Cin inner in chunks of 8 (Cin must be multiple of 8).
__global__ __launch_bounds__(256, 2) void conv3x3_tf32_kernel(
    const float* __restrict__ in, const float* __restrict__ wt,
    const float* __restrict__ bias, float* __restrict__ out,
    const float* __restrict__ addsrc, int Cin, int Cout, int doRelu)
{
    __shared__ float sIn[8 * SIN_CI];   // [ci][r*130 + c], rows r-1..r+1, cols -1..128
    __shared__ float sW[9][512];        // [k][co*8 + kk]

    const int row  = blockIdx.x;
    const int img  = blockIdx.y;
    const int coT  = blockIdx.z << 6;
    const int tid  = threadIdx.x;
    const int lane = tid & 31;
    const int warp = tid >> 5;
    const int g    = lane >> 2;
    const int t4   = lane & 3;
    const int wM   = warp & 1;
    const int wN   = warp >> 1;

    float acc[2][4][4];
#pragma unroll
    for (int i = 0; i < 2; i++)
#pragma unroll
        for (int j = 0; j < 4; j++)
#pragma unroll
            for (int l = 0; l < 4; l++) acc[i][j][l] = 0.f;

    const float* inImg = in + (size_t)img * Cin * HW;
    const size_t wBase = (size_t)coT * Cin * 9;

    for (int ci0 = 0; ci0 < Cin; ci0 += 8) {
        // ---- stage input tile: 8 ci x 3 rows x 130 cols (zero padded) ----
        for (int idx = tid; idx < 8 * 390; idx += 256) {
            int ci  = idx / 390;
            int rem = idx - ci * 390;
            int r   = rem / 130;
            int c   = rem - r * 130;
            int gr  = row - 1 + r;
            int gc  = c - 1;
            float v = 0.f;
            if ((unsigned)gr < HH && (unsigned)gc < WW)
                v = inImg[(size_t)(ci0 + ci) * HW + gr * WW + gc];
            sIn[ci * SIN_CI + r * 130 + c] = to_tf32(v);
        }
        // ---- stage weights: sW[k][co*8+kk] = W[coT+co][ci0+kk][k] ----
        for (int idx = tid; idx < 4608; idx += 256) {
            int k   = idx >> 9;
            int rem = idx & 511;
            int co  = rem >> 3;
            int kk  = rem & 7;
            float v = 0.f;
            if (coT + co < Cout)
                v = wt[wBase + (size_t)co * Cin * 9 + (size_t)(ci0 + kk) * 9 + k];
            sW[k][co * 8 + kk] = to_tf32(v);
        }
        __syncthreads();

#pragma unroll
        for (int ky = 0; ky < 3; ky++) {
#pragma unroll
            for (int kx = 0; kx < 3; kx++) {
                const int k = ky * 3 + kx;
                const float* wk = sW[k];
                const int aoff = (wM * 32 + g) * 8 + t4;
                float a[2][4];
#pragma unroll
                for (int mi = 0; mi < 2; mi++) {
                    a[mi][0] = wk[aoff + mi * 128];
                    a[mi][1] = wk[aoff + mi * 128 + 64];
                    a[mi][2] = wk[aoff + mi * 128 + 4];
                    a[mi][3] = wk[aoff + mi * 128 + 68];
                }
                const int boff = t4 * SIN_CI + ky * 130 + kx + wN * 32 + g;
                float b[4][2];
#pragma unroll
                for (int ni = 0; ni < 4; ni++) {
                    b[ni][0] = sIn[boff + ni * 8];
                    b[ni][1] = sIn[boff + 4 * SIN_CI + ni * 8];
                }
#pragma unroll
                for (int mi = 0; mi < 2; mi++)
#pragma unroll
                    for (int ni = 0; ni < 4; ni++)
                        mma_tf32(acc[mi][ni], a[mi], b[ni]);
            }
        }
        __syncthreads();
    }

    // ---- epilogue: bias (+residual) (+relu), float2 stores ----
#pragma unroll
    for (int mi = 0; mi < 2; mi++) {
#pragma unroll
        for (int rr = 0; rr < 2; rr++) {
            const int co = coT + wM * 32 + mi * 16 + rr * 8 + g;
            if (co < Cout) {
                const float bv = bias[co];
                const size_t base = ((size_t)img * Cout + co) * HW + row * WW + wN * 32 + 2 * t4;
#pragma unroll
                for (int ni = 0; ni < 4; ni++) {
                    float v0 = acc[mi][ni][rr * 2 + 0] + bv;
                    float v1 = acc[mi][ni][rr * 2 + 1] + bv;
                    const size_t idx = base + ni * 8;
                    if (addsrc) {
                        float2 r2 = *(const float2*)&addsrc[idx];
                        v0 += r2.x; v1 += r2.y;
                    }
                    if (doRelu) { v0 = fmaxf(v0, 0.f); v1 = fmaxf(v1, 0.f); }
                    *(float2*)&out[idx] = make_float2(v0, v1);
                }
            }
        }
    }
}

// ---------------- tf32 GEMM over DCN col buffer (Cout=64, K=576) ----------------
__global__ __launch_bounds__(256, 2) void gemm_tf32_kernel(
    const float* __restrict__ wt,   // [64][576]
    const float* __restrict__ colb, // [img][576][HW]
    const float* __restrict__ bias,
    float* __restrict__ out)        // [img][64][HW]
{
    __shared__ float sB[2][8 * 136];  // 136 % 32 == 8 -> conflict-free B frags
    __shared__ float sA[2][512];      // [co*8 + kk]

    const int pxb  = blockIdx.x << 7;
    const int img  = blockIdx.y;
    const int tid  = threadIdx.x;
    const int lane = tid & 31;
    const int warp = tid >> 5;
    const int g    = lane >> 2;
    const int t4   = lane & 3;
    const int wM   = warp & 1;
    const int wN   = warp >> 1;

    float acc[2][4][4];
#pragma unroll
    for (int i = 0; i < 2; i++)
#pragma unroll
        for (int j = 0; j < 4; j++)
#pragma unroll
            for (int l = 0; l < 4; l++) acc[i][j][l] = 0.f;

    const float* colImg = colb + (size_t)img * 576 * HW;

    for (int k0 = 0; k0 < 576; k0 += 16) {
        // B: 2 planes x 8 k x 128 px (512 float4 total, 2 per thread)
#pragma unroll
        for (int i = 0; i < 2; i++) {
            int idx = tid + i * 256;
            int s   = idx >> 8;
            int kk  = (idx >> 5) & 7;
            int c4  = idx & 31;
            float4 v = *(const float4*)&colImg[(size_t)(k0 + s * 8 + kk) * HW + pxb + c4 * 4];
            float* dst = &sB[s][kk * 136 + c4 * 4];
            dst[0] = to_tf32(v.x); dst[1] = to_tf32(v.y);
            dst[2] = to_tf32(v.z); dst[3] = to_tf32(v.w);
        }
        // A: 2 planes x 64 co x 8 kk (1024 floats, 4 per thread)
#pragma unroll
        for (int i = 0; i < 4; i++) {
            int idx = tid + i * 256;
            int s   = idx >> 9;
            int co  = (idx >> 3) & 63;
            int kk  = idx & 7;
            sA[s][co * 8 + kk] = to_tf32(wt[(size_t)co * 576 + k0 + s * 8 + kk]);
        }
        __syncthreads();

#pragma unroll
        for (int s = 0; s < 2; s++) {
            const float* As = sA[s];
            const float* Bs = sB[s];
            const int aoff = (wM * 32 + g) * 8 + t4;
            float a[2][4];
#pragma unroll
            for (int mi = 0; mi < 2; mi++) {
                a[mi][0] = As[aoff + mi * 128];
                a[mi][1] = As[aoff + mi * 128 + 64];
                a[mi][2] = As[aoff + mi * 128 + 4];
                a[mi][3] = As[aoff + mi * 128 + 68];
            }
            const int boff = t4 * 136 + wN * 32 + g;
            float b[4][2];
#pragma unroll
            for (int ni = 0; ni < 4; ni++) {
                b[ni][0] = Bs[boff + ni * 8];
                b[ni][1] = Bs[boff + 544 + ni * 8];
            }
#pragma unroll
            for (int mi = 0; mi < 2; mi++)
#pragma unroll
                for (int ni = 0; ni < 4; ni++)
                    mma_tf32(acc[mi][ni], a[mi], b[ni]);
        }
        __syncthreads();
    }

#pragma unroll
    for (int mi = 0; mi < 2; mi++) {
#pragma unroll
        for (int rr = 0; rr < 2; rr++) {
            const int co = wM * 32 + mi * 16 + rr * 8 + g;
            const float bv = bias[co];
            const size_t base = ((size_t)img * 64 + co) * HW + pxb + wN * 32 + 2 * t4;
#pragma unroll
            for (int ni = 0; ni < 4; ni++) {
                *(float2*)&out[base + ni * 8] =
                    make_float2(acc[mi][ni][rr * 2 + 0] + bv, acc[mi][ni][rr * 2 + 1] + bv);
            }
        }
    }
}

// ---------------- FFMA 3x3 conv (kept for Cin=1 / Cout=1 cases) ----------------
__global__ __launch_bounds__(256, 2) void conv3x3_kernel(
    const float* __restrict__ in, const float* __restrict__ wt,
    const float* __restrict__ bias, float* __restrict__ out,
    const float* __restrict__ addsrc,
    int Cin, int Cout, int doRelu)
{
    __shared__ __align__(16) float sIn[CHUNK][18][80];
    __shared__ __align__(16) float sW[CHUNK][9][16];

    const int tw  = blockIdx.x & 1;
    const int th  = blockIdx.x >> 1;
    const int img = blockIdx.y;
    const int cob = blockIdx.z * 16;
    const int tid = threadIdx.x;
    const int tx  = tid & 15;
    const int ty  = tid >> 4;

    float acc[4][16];
#pragma unroll
    for (int p = 0; p < 4; p++)
#pragma unroll
        for (int c = 0; c < 16; c++) acc[p][c] = 0.f;

    const int nch = (Cin + CHUNK - 1) / CHUNK;
    for (int cc = 0; cc < nch; cc++) {
        const int cin0 = cc * CHUNK;
        for (int idx = tid; idx < CHUNK * 18 * 66; idx += 256) {
            int ci  = idx / (18 * 66);
            int rem = idx - ci * (18 * 66);
            int r = rem / 66, c = rem - r * 66;
            int gr = th * 16 + r - 1;
            int gc = tw * 64 + c - 1;
            int cin = cin0 + ci;
            float v = 0.f;
            if (cin < Cin && gr >= 0 && gr < HH && gc >= 0 && gc < WW)
                v = in[((size_t)img * Cin + cin) * HW + gr * WW + gc];
            sIn[ci][r][c] = v;
        }
        for (int idx = tid; idx < CHUNK * 9 * 16; idx += 256) {
            int ci  = idx / 144;
            int rem = idx - ci * 144;
            int k = rem >> 4, co = rem & 15;
            int cin = cin0 + ci;
            float v = 0.f;
            if (cin < Cin && (cob + co) < Cout)
                v = wt[((size_t)(cob + co) * Cin + cin) * 9 + k];
            sW[ci][k][co] = v;
        }
        __syncthreads();

        for (int ci = 0; ci < CHUNK; ci++) {
#pragma unroll
            for (int k = 0; k < 9; k++) {
                const int ky = k / 3, kx = k - ky * 3;
                const float4 w0 = *(const float4*)&sW[ci][k][0];
                const float4 w1 = *(const float4*)&sW[ci][k][4];
                const float4 w2 = *(const float4*)&sW[ci][k][8];
                const float4 w3 = *(const float4*)&sW[ci][k][12];
                const float wv[16] = {w0.x, w0.y, w0.z, w0.w, w1.x, w1.y, w1.z, w1.w,
                                      w2.x, w2.y, w2.z, w2.w, w3.x, w3.y, w3.z, w3.w};
#pragma unroll
                for (int p = 0; p < 4; p++) {
                    const float xv = sIn[ci][ty + ky][tx + 16 * p + kx];
#pragma unroll
                    for (int co = 0; co < 16; co++)
                        acc[p][co] = fmaf(xv, wv[co], acc[p][co]);
                }
            }
        }
        __syncthreads();
    }

    const int row = th * 16 + ty;
    const int colb = tw * 64 + tx;
#pragma unroll
    for (int co = 0; co < 16; co++) {
        const int oc = cob + co;
        if (oc < Cout) {
            const float b = bias[oc];
#pragma unroll
            for (int p = 0; p < 4; p++) {
                const size_t idx = ((size_t)img * Cout + oc) * HW + row * WW + colb + 16 * p;
                float v = acc[p][co] + b;
                if (addsrc) v += addsrc[idx];
                if (doRelu) v = fmaxf(v, 0.f);
                out[idx] = v;
            }
        }
    }
}

// ---------------- pack [ref | nei] concat buffer ----------------
__global__ void pack_cat_kernel(const float* __restrict__ feat, float* __restrict__ cat)
{
    const int gid = blockIdx.x * 256 + threadIdx.x;
    const int px = gid & (HW - 1);
    const int t  = gid >> 14;
    const int ch = t & 127;
    const int j  = t >> 7;
    const int b  = j / 5;
    float v;
    if (ch < 64) v = feat[((size_t)(b * 5 + 2) * 64 + ch) * HW + px];
    else         v = feat[((size_t)j * 64 + (ch - 64)) * HW + px];
    cat[gid] = v;
}

// ---------------- modulated deformable im2col (DCNv2) ----------------
__global__ void dcn_im2col_kernel(const float* __restrict__ x,
                                  const float* __restrict__ om,
                                  float* __restrict__ col)
{
    const int gid = blockIdx.x * 256 + threadIdx.x;
    const int px = gid & (HW - 1);
    const int t  = gid >> 14;
    const int gk = t % 72;
    const int j  = t / 72;
    const int g  = gk / 9, k = gk - g * 9;
    const int h  = px >> 7, w = px & 127;

    const float* omj = om + (size_t)j * 216 * HW;
    const float dy = omj[(size_t)(gk)       * HW + px];
    const float dx = omj[(size_t)(72  + gk) * HW + px];
    float m        = omj[(size_t)(144 + gk) * HW + px];
    m = 1.f / (1.f + expf(-m));

    const float py  = (float)h + (float)(k / 3 - 1) + dy;
    const float pxf = (float)w + (float)(k % 3 - 1) + dx;
    const float y0f = floorf(py), x0f = floorf(pxf);
    const float wy = py - y0f, wx = pxf - x0f;
    const int y0 = (int)y0f, x0 = (int)x0f;
    const int y1 = y0 + 1,   x1 = x0 + 1;
    const bool vy0 = (y0 >= 0) & (y0 < HH), vy1 = (y1 >= 0) & (y1 < HH);
    const bool vx0 = (x0 >= 0) & (x0 < WW), vx1 = (x1 >= 0) & (x1 < WW);
    const int cy0 = min(max(y0, 0), HH - 1), cy1 = min(max(y1, 0), HH - 1);
    const int cx0 = min(max(x0, 0), WW - 1), cx1 = min(max(x1, 0), WW - 1);
    const float w00 = (1.f - wy) * (1.f - wx) * m * ((vy0 && vx0) ? 1.f : 0.f);
    const float w01 = (1.f - wy) * wx         * m * ((vy0 && vx1) ? 1.f : 0.f);
    const float w10 = wy * (1.f - wx)         * m * ((vy1 && vx0) ? 1.f : 0.f);
    const float w11 = wy * wx                 * m * ((vy1 && vx1) ? 1.f : 0.f);

    const int i00 = cy0 * WW + cx0, i01 = cy0 * WW + cx1;
    const int i10 = cy1 * WW + cx0, i11 = cy1 * WW + cx1;

    const float* xg = x + ((size_t)j * 64 + g * 8) * HW;
    const size_t colbase = ((size_t)j * 576 + (size_t)(g * 8) * 9 + k) * HW + px;
#pragma unroll
    for (int c = 0; c < 8; c++) {
        const float* xc = xg + (size_t)c * HW;
        const float v = w00 * xc[i00] + w01 * xc[i01] + w10 * xc[i10] + w11 * xc[i11];
        col[colbase + (size_t)c * 9 * HW] = v;
    }
}

// ---------------- host launcher ----------------
static inline void launch_conv_ffma(const float* in, const float* w, const float* b,
                                    float* out, const float* add,
                                    int Cin, int Cout, int relu)
{
    dim3 grid(16, NIMG, (Cout + 15) / 16);
    conv3x3_kernel<<<grid, 256>>>(in, w, b, out, add, Cin, Cout, relu);
}

static inline void launch_conv_tf32(const float* in, const float* w, const float* b,
                                    float* out, const float* add,
                                    int Cin, int Cout, int relu)
{
    dim3 grid(HH, NIMG, (Cout + 63) / 64);
    conv3x3_tf32_kernel<<<grid, 256>>>(in, w, b, out, add, Cin, Cout, relu);
}

extern "C" void kernel_launch(void* const* d_in, const int* in_sizes, int n_in,
                              void* d_out, int out_size)
{
    const float* x       = (const float*)d_in[0];
    const float* w_init  = (const float*)d_in[1];
    const float* b_init  = (const float*)d_in[2];
    const float* res_w1  = (const float*)d_in[3];
    const float* res_b1  = (const float*)d_in[4];
    const float* res_w2  = (const float*)d_in[5];
    const float* res_b2  = (const float*)d_in[6];
    const float* w_bn    = (const float*)d_in[7];
    const float* b_bn    = (const float*)d_in[8];
    const float* off_w   = (const float*)d_in[9];
    const float* off_b   = (const float*)d_in[10];
    const float* com_w   = (const float*)d_in[11];
    const float* com_b   = (const float*)d_in[12];
    const float* dcn_w   = (const float*)d_in[13];
    const float* dcn_b   = (const float*)d_in[14];
    const float* w_rec   = (const float*)d_in[15];
    const float* b_rec   = (const float*)d_in[16];
    float* out = (float*)d_out;

    float *bufA, *bufB, *bufT, *cat, *om, *colb;
    cudaGetSymbolAddress((void**)&bufA, g_bufA);
    cudaGetSymbolAddress((void**)&bufB, g_bufB);
    cudaGetSymbolAddress((void**)&bufT, g_bufT);
    cudaGetSymbolAddress((void**)&cat,  g_cat);
    cudaGetSymbolAddress((void**)&om,   g_om);
    cudaGetSymbolAddress((void**)&colb, g_col);
    float* obuf = cat;

    // 1) init conv + relu  (Cin=1 -> FFMA path)
    launch_conv_ffma(x, w_init, b_init, bufA, nullptr, 1, 64, 1);

    // 2) 5 residual blocks (tf32 MMA)
    float* cur = bufA;
    float* nxt = bufB;
    for (int i = 0; i < 5; i++) {
        launch_conv_tf32(cur, res_w1 + (size_t)i * 64 * 64 * 9, res_b1 + i * 64, bufT, nullptr, 64, 64, 1);
        launch_conv_tf32(bufT, res_w2 + (size_t)i * 64 * 64 * 9, res_b2 + i * 64, nxt, cur, 64, 64, 0);
        float* t = cur; cur = nxt; nxt = t;
    }
    float* feat = cur;

    // 3) pack [ref | nei] and bottleneck conv (Cin=128)
    pack_cat_kernel<<<(NIMG * 128 * HW) / 256, 256>>>(feat, cat);
    launch_conv_tf32(cat, w_bn, b_bn, bufA, nullptr, 128, 64, 0);

    // 4) four chained DCN stages
    dim3 ggemm(HW / 128, NIMG, 1);
    const int im2colBlocks = (NIMG * 72 * HW) / 256;

    auto dcn_stage = [&](const float* xsrc, const float* feaSrc, int di, float* outBuf) {
        launch_conv_tf32(feaSrc, off_w + (size_t)di * 64 * 64 * 9, off_b + di * 64, obuf, nullptr, 64, 64, 0);
        launch_conv_tf32(obuf, com_w + (size_t)di * 216 * 64 * 9, com_b + di * 216, om, nullptr, 64, 216, 0);
        dcn_im2col_kernel<<<im2colBlocks, 256>>>(xsrc, om, colb);
        gemm_tf32_kernel<<<ggemm, 256>>>(dcn_w + (size_t)di * 64 * 64 * 9, colb,
                                         dcn_b + di * 64, outBuf);
    };

    dcn_stage(bufA, bufA, 0, bufT);   // fea = dcn(fea, o0)
    dcn_stage(bufT, bufT, 1, bufA);   // fea = dcn(fea, o1)
    dcn_stage(feat, bufA, 2, bufT);   // fea = dcn(nei, o2)
    dcn_stage(bufT, bufT, 3, bufA);   // aligned = dcn(fea, o3)

    // 5) reconstruction conv (Cout=1 -> FFMA path) straight into d_out
    launch_conv_ffma(bufA, w_rec, b_rec, out, nullptr, 64, 1, 0);
}

// round 4
// speedup vs baseline: 2.8203x; 1.5800x over previous
#include <cuda_runtime.h>
#include <math.h>
#include <stdint.h>

#define HH 128
#define WW 128
#define HW 16384
#define NIMG 20
#define CHUNK 4

// ---------------- scratch (device globals; no allocation allowed) ----------------
__device__ float g_bufA[(size_t)NIMG * 64 * HW];
__device__ float g_bufB[(size_t)NIMG * 64 * HW];
__device__ float g_bufT[(size_t)NIMG * 64 * HW];
__device__ float g_cat [(size_t)NIMG * 128 * HW];
__device__ float g_om  [(size_t)NIMG * 216 * HW];
__device__ float g_col [(size_t)NIMG * 576 * HW];
__device__ float g_wprep[1327104];   // prepped tf32 fragment-layout weights

// ---------------- helpers ----------------
__device__ __forceinline__ uint32_t smem_u32(const void* p) {
    uint32_t a;
    asm("{ .reg .u64 t; cvta.to.shared.u64 t, %1; cvt.u32.u64 %0, t; }" : "=r"(a) : "l"(p));
    return a;
}
__device__ __forceinline__ float to_tf32(float v) {
    unsigned u; asm("cvt.rna.tf32.f32 %0, %1;" : "=r"(u) : "f"(v));
    return __uint_as_float(u);
}
__device__ __forceinline__ void cp16(uint32_t dst, const void* src, unsigned nbytes) {
    asm volatile("cp.async.cg.shared.global [%0], [%1], 16, %2;"
                 :: "r"(dst), "l"(src), "r"(nbytes) : "memory");
}
__device__ __forceinline__ void cp_commit() {
    asm volatile("cp.async.commit_group;" ::: "memory");
}
__device__ __forceinline__ void cp_wait1() {
    asm volatile("cp.async.wait_group 1;" ::: "memory");
}
__device__ __forceinline__ void cp_wait0() {
    asm volatile("cp.async.wait_group 0;" ::: "memory");
}
__device__ __forceinline__ void mma_tf32(float* c, const float* a, const float* b) {
    asm volatile(
        "mma.sync.aligned.m16n8k8.row.col.f32.tf32.tf32.f32 "
        "{%0,%1,%2,%3}, {%4,%5,%6,%7}, {%8,%9}, {%0,%1,%2,%3};"
        : "+f"(c[0]), "+f"(c[1]), "+f"(c[2]), "+f"(c[3])
        : "r"(__float_as_uint(a[0])), "r"(__float_as_uint(a[1])),
          "r"(__float_as_uint(a[2])), "r"(__float_as_uint(a[3])),
          "r"(__float_as_uint(b[0])), "r"(__float_as_uint(b[1])));
}

// ---------------- weight prep: conv [Cout,Cin,9] -> per-chunk fragment images ----------------
// dst layout: [zb][ky][cc][kx(3)][wM(2)][mi(2)][lane(32)][q(4)]  (1536 floats per (zb,ky,cc))
__global__ void prep_conv_kernel(const float* __restrict__ w, float* __restrict__ dst,
                                 int Cin, int Cout, int total)
{
    const int gid = blockIdx.x * 256 + threadIdx.x;
    if (gid >= total) return;
    const int q    = gid & 3;
    const int lane = (gid >> 2) & 31;
    const int mi   = (gid >> 7) & 1;
    const int wM   = (gid >> 8) & 1;
    const int kx   = (gid >> 9) % 3;
    const int t    = gid / 1536;
    const int nci  = Cin >> 3;
    const int cc   = t % nci;
    const int t2   = t / nci;
    const int ky   = t2 % 3;
    const int zb   = t2 / 3;
    const int g    = lane >> 2, t4 = lane & 3;
    const int co   = zb * 64 + wM * 32 + mi * 16 + ((q & 1) << 3) + g;
    const int ci   = cc * 8 + t4 + ((q >> 1) << 2);
    const int k    = ky * 3 + kx;
    float v = (co < Cout) ? w[((size_t)co * Cin + ci) * 9 + k] : 0.f;
    dst[gid] = to_tf32(v);
}

// dst layout: [ch(36)][s(2)][wM][mi][lane][q]  (1024 floats per chunk), W:[64,576]
__global__ void prep_gemm_kernel(const float* __restrict__ w, float* __restrict__ dst)
{
    const int gid = blockIdx.x * 256 + threadIdx.x;   // 36864 total
    const int q    = gid & 3;
    const int lane = (gid >> 2) & 31;
    const int mi   = (gid >> 7) & 1;
    const int wM   = (gid >> 8) & 1;
    const int s    = (gid >> 9) & 1;
    const int ch   = gid >> 10;
    const int co   = wM * 32 + mi * 16 + ((q & 1) << 3) + (lane >> 2);
    const int kk   = (lane & 3) + ((q >> 1) << 2);
    dst[gid] = to_tf32(w[(size_t)co * 576 + ch * 16 + s * 8 + kk]);
}

// ---------------- tf32 implicit-GEMM 3x3 SAME conv, cp.async pipelined ----------------
// Block 256 thr = 8 warps (2M x 4N). Tile: 64 Cout x 128 px (one row). Chunk = (ky, 8 ci).
__global__ __launch_bounds__(256, 3) void conv3x3_tc2(
    const float* __restrict__ in, const float* __restrict__ wp,
    const float* __restrict__ bias, float* __restrict__ out,
    const float* __restrict__ addsrc, int Cin, int Cout, int flags)
{
    __shared__ __align__(16) float sIn[2][1088];    // [ci(8)][136]: gc=0 at col 4
    __shared__ __align__(16) float sWq[2][1536];    // [kx(3)][512] fragment-vector image

    const int row  = blockIdx.x;
    const int img  = blockIdx.y;
    const int zb   = blockIdx.z;
    const int coT  = zb << 6;
    const int tid  = threadIdx.x;
    const int warp = tid >> 5;
    const int lane = tid & 31;
    const int g    = lane >> 2, t4 = lane & 3;
    const int wM   = warp & 1,  wN = warp >> 1;
    const int nci  = Cin >> 3;
    const int nch  = 3 * nci;

    const uint32_t sInB = smem_u32(sIn);
    const uint32_t sWB  = smem_u32(sWq);
    const float* inImg = in + (size_t)img * Cin * HW;
    const float* wpL   = wp + (size_t)zb * nch * 1536;

    float acc[2][4][4];
#pragma unroll
    for (int i = 0; i < 2; i++)
#pragma unroll
        for (int j = 0; j < 4; j++)
#pragma unroll
            for (int l = 0; l < 4; l++) acc[i][j][l] = 0.f;

    // zero the two halo columns (gc=-1 -> col 3, gc=128 -> col 132) in both buffers
    if (tid < 32) {
        const int b = tid >> 4, ci = (tid >> 1) & 7, h = tid & 1;
        sIn[b][ci * 136 + (h ? 132 : 3)] = 0.f;
    }

    auto loadChunk = [&](int c, int buf) {
        const int ky = c / nci, cc = c - ky * nci;
        int gr = row + ky - 1;
        const unsigned rs = ((unsigned)gr < HH) ? 16u : 0u;
        if (gr < 0) gr = 0; else if (gr > HH - 1) gr = HH - 1;
        // input: 8 ci x 32 float4 (one per thread)
        {
            const int ci = tid >> 5, j = tid & 31;
            cp16(sInB + (buf * 1088 + ci * 136 + 4 + 4 * j) * 4,
                 inImg + (size_t)(cc * 8 + ci) * HW + gr * WW + 4 * j, rs);
        }
        // weights: 384 float4 contiguous
        const float* ws = wpL + (size_t)c * 1536;
#pragma unroll
        for (int i = tid; i < 384; i += 256)
            cp16(sWB + (buf * 1536 + 4 * i) * 4, ws + 4 * i, 16);
        cp_commit();
    };

    loadChunk(0, 0);
    for (int c = 0; c < nch; c++) {
        const int buf = c & 1;
        if (c + 1 < nch) { loadChunk(c + 1, buf ^ 1); cp_wait1(); }
        else             { cp_wait0(); }
        __syncthreads();

        const float* sI  = sIn[buf];
        const float* sWb = sWq[buf];
#pragma unroll
        for (int kx = 0; kx < 3; kx++) {
            const float4 a0 = *(const float4*)&sWb[kx * 512 + wM * 256 + lane * 4];
            const float4 a1 = *(const float4*)&sWb[kx * 512 + wM * 256 + 128 + lane * 4];
            const int bo = t4 * 136 + 3 + kx + wN * 32 + g;
#pragma unroll
            for (int ni = 0; ni < 4; ni++) {
                float b2[2] = { sI[bo + ni * 8], sI[bo + 544 + ni * 8] };
                mma_tf32(acc[0][ni], (const float*)&a0, b2);
                mma_tf32(acc[1][ni], (const float*)&a1, b2);
            }
        }
        __syncthreads();
    }

    // epilogue
    const int doRelu  = flags & 1;
    const int doRound = flags & 2;
#pragma unroll
    for (int mi = 0; mi < 2; mi++) {
#pragma unroll
        for (int rr = 0; rr < 2; rr++) {
            const int co = coT + wM * 32 + mi * 16 + rr * 8 + g;
            if (co < Cout) {
                const float bv = bias[co];
                const size_t base = ((size_t)img * Cout + co) * HW + row * WW + wN * 32 + 2 * t4;
#pragma unroll
                for (int ni = 0; ni < 4; ni++) {
                    float v0 = acc[mi][ni][rr * 2 + 0] + bv;
                    float v1 = acc[mi][ni][rr * 2 + 1] + bv;
                    const size_t idx = base + ni * 8;
                    if (addsrc) {
                        float2 r2 = *(const float2*)&addsrc[idx];
                        v0 += r2.x; v1 += r2.y;
                    }
                    if (doRelu) { v0 = fmaxf(v0, 0.f); v1 = fmaxf(v1, 0.f); }
                    if (doRound) { v0 = to_tf32(v0); v1 = to_tf32(v1); }
                    *(float2*)&out[idx] = make_float2(v0, v1);
                }
            }
        }
    }
}

// ---------------- tf32 GEMM over DCN col buffer (Cout=64, K=576), pipelined ----------------
__global__ __launch_bounds__(256, 3) void gemm_tc2(
    const float* __restrict__ wp,   // prepped [36][1024]
    const float* __restrict__ colb, // [img][576][HW] (tf32-rounded)
    const float* __restrict__ bias,
    float* __restrict__ out)        // [img][64][HW]
{
    __shared__ __align__(16) float sB[2][2176];   // [kk16(16)][136]
    __shared__ __align__(16) float sA[2][1024];   // [s(2)][512] fragment-vector image

    const int pxb  = blockIdx.x << 7;
    const int img  = blockIdx.y;
    const int tid  = threadIdx.x;
    const int warp = tid >> 5;
    const int lane = tid & 31;
    const int g    = lane >> 2, t4 = lane & 3;
    const int wM   = warp & 1,  wN = warp >> 1;

    const uint32_t sBB = smem_u32(sB);
    const uint32_t sAB = smem_u32(sA);
    const float* colImg = colb + (size_t)img * 576 * HW;

    float acc[2][4][4];
#pragma unroll
    for (int i = 0; i < 2; i++)
#pragma unroll
        for (int j = 0; j < 4; j++)
#pragma unroll
            for (int l = 0; l < 4; l++) acc[i][j][l] = 0.f;

    auto loadChunk = [&](int c, int buf) {
        // col: 16 k x 32 float4 (2 per thread)
#pragma unroll
        for (int i = tid; i < 512; i += 256) {
            const int kk = i >> 5, j = i & 31;
            cp16(sBB + (buf * 2176 + kk * 136 + 4 * j) * 4,
                 colImg + (size_t)(c * 16 + kk) * HW + pxb + 4 * j, 16);
        }
        // weights: 256 float4 (1 per thread)
        cp16(sAB + (buf * 1024 + 4 * tid) * 4, wp + (size_t)c * 1024 + 4 * tid, 16);
        cp_commit();
    };

    loadChunk(0, 0);
    for (int c = 0; c < 36; c++) {
        const int buf = c & 1;
        if (c + 1 < 36) { loadChunk(c + 1, buf ^ 1); cp_wait1(); }
        else            { cp_wait0(); }
        __syncthreads();

        const float* sBb = sB[buf];
        const float* sAb = sA[buf];
#pragma unroll
        for (int s = 0; s < 2; s++) {
            const float4 a0 = *(const float4*)&sAb[s * 512 + wM * 256 + lane * 4];
            const float4 a1 = *(const float4*)&sAb[s * 512 + wM * 256 + 128 + lane * 4];
            const int bo = (s * 8 + t4) * 136 + wN * 32 + g;
#pragma unroll
            for (int ni = 0; ni < 4; ni++) {
                float b2[2] = { sBb[bo + ni * 8], sBb[bo + 544 + ni * 8] };
                mma_tf32(acc[0][ni], (const float*)&a0, b2);
                mma_tf32(acc[1][ni], (const float*)&a1, b2);
            }
        }
        __syncthreads();
    }

#pragma unroll
    for (int mi = 0; mi < 2; mi++) {
#pragma unroll
        for (int rr = 0; rr < 2; rr++) {
            const int co = wM * 32 + mi * 16 + rr * 8 + g;
            const float bv = bias[co];
            const size_t base = ((size_t)img * 64 + co) * HW + pxb + wN * 32 + 2 * t4;
#pragma unroll
            for (int ni = 0; ni < 4; ni++) {
                float v0 = to_tf32(acc[mi][ni][rr * 2 + 0] + bv);
                float v1 = to_tf32(acc[mi][ni][rr * 2 + 1] + bv);
                *(float2*)&out[base + ni * 8] = make_float2(v0, v1);
            }
        }
    }
}

// ---------------- FFMA 3x3 conv (Cin=1 / Cout=1 cases) ----------------
__global__ __launch_bounds__(256, 2) void conv3x3_kernel(
    const float* __restrict__ in, const float* __restrict__ wt,
    const float* __restrict__ bias, float* __restrict__ out,
    const float* __restrict__ addsrc,
    int Cin, int Cout, int doRelu, int doRound)
{
    __shared__ __align__(16) float sIn[CHUNK][18][80];
    __shared__ __align__(16) float sW[CHUNK][9][16];

    const int tw  = blockIdx.x & 1;
    const int th  = blockIdx.x >> 1;
    const int img = blockIdx.y;
    const int cob = blockIdx.z * 16;
    const int tid = threadIdx.x;
    const int tx  = tid & 15;
    const int ty  = tid >> 4;

    float acc[4][16];
#pragma unroll
    for (int p = 0; p < 4; p++)
#pragma unroll
        for (int c = 0; c < 16; c++) acc[p][c] = 0.f;

    const int nch = (Cin + CHUNK - 1) / CHUNK;
    for (int cc = 0; cc < nch; cc++) {
        const int cin0 = cc * CHUNK;
        for (int idx = tid; idx < CHUNK * 18 * 66; idx += 256) {
            int ci  = idx / (18 * 66);
            int rem = idx - ci * (18 * 66);
            int r = rem / 66, c = rem - r * 66;
            int gr = th * 16 + r - 1;
            int gc = tw * 64 + c - 1;
            int cin = cin0 + ci;
            float v = 0.f;
            if (cin < Cin && gr >= 0 && gr < HH && gc >= 0 && gc < WW)
                v = in[((size_t)img * Cin + cin) * HW + gr * WW + gc];
            sIn[ci][r][c] = v;
        }
        for (int idx = tid; idx < CHUNK * 9 * 16; idx += 256) {
            int ci  = idx / 144;
            int rem = idx - ci * 144;
            int k = rem >> 4, co = rem & 15;
            int cin = cin0 + ci;
            float v = 0.f;
            if (cin < Cin && (cob + co) < Cout)
                v = wt[((size_t)(cob + co) * Cin + cin) * 9 + k];
            sW[ci][k][co] = v;
        }
        __syncthreads();

        for (int ci = 0; ci < CHUNK; ci++) {
#pragma unroll
            for (int k = 0; k < 9; k++) {
                const int ky = k / 3, kx = k - ky * 3;
                const float4 w0 = *(const float4*)&sW[ci][k][0];
                const float4 w1 = *(const float4*)&sW[ci][k][4];
                const float4 w2 = *(const float4*)&sW[ci][k][8];
                const float4 w3 = *(const float4*)&sW[ci][k][12];
                const float wv[16] = {w0.x, w0.y, w0.z, w0.w, w1.x, w1.y, w1.z, w1.w,
                                      w2.x, w2.y, w2.z, w2.w, w3.x, w3.y, w3.z, w3.w};
#pragma unroll
                for (int p = 0; p < 4; p++) {
                    const float xv = sIn[ci][ty + ky][tx + 16 * p + kx];
#pragma unroll
                    for (int co = 0; co < 16; co++)
                        acc[p][co] = fmaf(xv, wv[co], acc[p][co]);
                }
            }
        }
        __syncthreads();
    }

    const int row = th * 16 + ty;
    const int colb2 = tw * 64 + tx;
#pragma unroll
    for (int co = 0; co < 16; co++) {
        const int oc = cob + co;
        if (oc < Cout) {
            const float b = bias[oc];
#pragma unroll
            for (int p = 0; p < 4; p++) {
                const size_t idx = ((size_t)img * Cout + oc) * HW + row * WW + colb2 + 16 * p;
                float v = acc[p][co] + b;
                if (addsrc) v += addsrc[idx];
                if (doRelu) v = fmaxf(v, 0.f);
                if (doRound) v = to_tf32(v);
                out[idx] = v;
            }
        }
    }
}

// ---------------- pack [ref | nei] concat buffer ----------------
__global__ void pack_cat_kernel(const float* __restrict__ feat, float* __restrict__ cat)
{
    const int gid = blockIdx.x * 256 + threadIdx.x;
    const int px = gid & (HW - 1);
    const int t  = gid >> 14;
    const int ch = t & 127;
    const int j  = t >> 7;
    const int b  = j / 5;
    float v;
    if (ch < 64) v = feat[((size_t)(b * 5 + 2) * 64 + ch) * HW + px];
    else         v = feat[((size_t)j * 64 + (ch - 64)) * HW + px];
    cat[gid] = v;
}

// ---------------- modulated deformable im2col (DCNv2), tf32-rounded output ----------------
__global__ void dcn_im2col_kernel(const float* __restrict__ x,
                                  const float* __restrict__ om,
                                  float* __restrict__ col)
{
    const int gid = blockIdx.x * 256 + threadIdx.x;
    const int px = gid & (HW - 1);
    const int t  = gid >> 14;
    const int gk = t % 72;
    const int j  = t / 72;
    const int g  = gk / 9, k = gk - g * 9;
    const int h  = px >> 7, w = px & 127;

    const float* omj = om + (size_t)j * 216 * HW;
    const float dy = omj[(size_t)(gk)       * HW + px];
    const float dx = omj[(size_t)(72  + gk) * HW + px];
    float m        = omj[(size_t)(144 + gk) * HW + px];
    m = 1.f / (1.f + expf(-m));

    const float py  = (float)h + (float)(k / 3 - 1) + dy;
    const float pxf = (float)w + (float)(k % 3 - 1) + dx;
    const float y0f = floorf(py), x0f = floorf(pxf);
    const float wy = py - y0f, wx = pxf - x0f;
    const int y0 = (int)y0f, x0 = (int)x0f;
    const int y1 = y0 + 1,   x1 = x0 + 1;
    const bool vy0 = (y0 >= 0) & (y0 < HH), vy1 = (y1 >= 0) & (y1 < HH);
    const bool vx0 = (x0 >= 0) & (x0 < WW), vx1 = (x1 >= 0) & (x1 < WW);
    const int cy0 = min(max(y0, 0), HH - 1), cy1 = min(max(y1, 0), HH - 1);
    const int cx0 = min(max(x0, 0), WW - 1), cx1 = min(max(x1, 0), WW - 1);
    const float w00 = (1.f - wy) * (1.f - wx) * m * ((vy0 && vx0) ? 1.f : 0.f);
    const float w01 = (1.f - wy) * wx         * m * ((vy0 && vx1) ? 1.f : 0.f);
    const float w10 = wy * (1.f - wx)         * m * ((vy1 && vx0) ? 1.f : 0.f);
    const float w11 = wy * wx                 * m * ((vy1 && vx1) ? 1.f : 0.f);

    const int i00 = cy0 * WW + cx0, i01 = cy0 * WW + cx1;
    const int i10 = cy1 * WW + cx0, i11 = cy1 * WW + cx1;

    const float* xg = x + ((size_t)j * 64 + g * 8) * HW;
    const size_t colbase = ((size_t)j * 576 + (size_t)(g * 8) * 9 + k) * HW + px;
#pragma unroll
    for (int c = 0; c < 8; c++) {
        const float* xc = xg + (size_t)c * HW;
        const float v = w00 * xc[i00] + w01 * xc[i01] + w10 * xc[i10] + w11 * xc[i11];
        col[colbase + (size_t)c * 9 * HW] = to_tf32(v);
    }
}

// ---------------- host launcher ----------------
static inline void launch_conv_ffma(const float* in, const float* w, const float* b,
                                    float* out, const float* add,
                                    int Cin, int Cout, int relu, int roundOut)
{
    dim3 grid(16, NIMG, (Cout + 15) / 16);
    conv3x3_kernel<<<grid, 256>>>(in, w, b, out, add, Cin, Cout, relu, roundOut);
}

static inline void launch_conv_tc(const float* in, const float* wp, const float* b,
                                  float* out, const float* add,
                                  int Cin, int Cout, int flags)
{
    dim3 grid(HH, NIMG, (Cout + 63) / 64);
    conv3x3_tc2<<<grid, 256>>>(in, wp, b, out, add, Cin, Cout, flags);
}

extern "C" void kernel_launch(void* const* d_in, const int* in_sizes, int n_in,
                              void* d_out, int out_size)
{
    const float* x       = (const float*)d_in[0];
    const float* w_init  = (const float*)d_in[1];
    const float* b_init  = (const float*)d_in[2];
    const float* res_w1  = (const float*)d_in[3];
    const float* res_b1  = (const float*)d_in[4];
    const float* res_w2  = (const float*)d_in[5];
    const float* res_b2  = (const float*)d_in[6];
    const float* w_bn    = (const float*)d_in[7];
    const float* b_bn    = (const float*)d_in[8];
    const float* off_w   = (const float*)d_in[9];
    const float* off_b   = (const float*)d_in[10];
    const float* com_w   = (const float*)d_in[11];
    const float* com_b   = (const float*)d_in[12];
    const float* dcn_w   = (const float*)d_in[13];
    const float* dcn_b   = (const float*)d_in[14];
    const float* w_rec   = (const float*)d_in[15];
    const float* b_rec   = (const float*)d_in[16];
    float* out = (float*)d_out;

    float *bufA, *bufB, *bufT, *cat, *om, *colb, *wprep;
    cudaGetSymbolAddress((void**)&bufA, g_bufA);
    cudaGetSymbolAddress((void**)&bufB, g_bufB);
    cudaGetSymbolAddress((void**)&bufT, g_bufT);
    cudaGetSymbolAddress((void**)&cat,  g_cat);
    cudaGetSymbolAddress((void**)&om,   g_om);
    cudaGetSymbolAddress((void**)&colb, g_col);
    cudaGetSymbolAddress((void**)&wprep, g_wprep);
    float* obuf = cat;

    // ---- weight prep (tiny launches) ----
    size_t off = 0;
    auto prepConv = [&](const float* w, int Cin, int Cout) -> const float* {
        float* d = wprep + off;
        const int zb = (Cout + 63) / 64;
        const int tot = zb * 3 * (Cin / 8) * 1536;
        prep_conv_kernel<<<(tot + 255) / 256, 256>>>(w, d, Cin, Cout, tot);
        off += (size_t)tot;
        return d;
    };
    auto prepGemm = [&](const float* w) -> const float* {
        float* d = wprep + off;
        prep_gemm_kernel<<<144, 256>>>(w, d);
        off += 36864;
        return d;
    };

    const float* pw_r1[5]; const float* pw_r2[5];
    for (int i = 0; i < 5; i++) pw_r1[i] = prepConv(res_w1 + (size_t)i * 36864, 64, 64);
    for (int i = 0; i < 5; i++) pw_r2[i] = prepConv(res_w2 + (size_t)i * 36864, 64, 64);
    const float* pw_bn = prepConv(w_bn, 128, 64);
    const float* pw_off[4]; const float* pw_com[4]; const float* pw_gemm[4];
    for (int d = 0; d < 4; d++) pw_off[d]  = prepConv(off_w + (size_t)d * 36864, 64, 64);
    for (int d = 0; d < 4; d++) pw_com[d]  = prepConv(com_w + (size_t)d * 216 * 64 * 9, 64, 216);
    for (int d = 0; d < 4; d++) pw_gemm[d] = prepGemm(dcn_w + (size_t)d * 36864);

    // ---- network ----
    // 1) init conv + relu (Cin=1, FFMA), round output to tf32
    launch_conv_ffma(x, w_init, b_init, bufA, nullptr, 1, 64, 1, 1);

    // 2) 5 residual blocks
    float* cur = bufA;
    float* nxt = bufB;
    for (int i = 0; i < 5; i++) {
        launch_conv_tc(cur, pw_r1[i], res_b1 + i * 64, bufT, nullptr, 64, 64, 1 | 2);
        launch_conv_tc(bufT, pw_r2[i], res_b2 + i * 64, nxt, cur, 64, 64, 2);
        float* t = cur; cur = nxt; nxt = t;
    }
    float* feat = cur;

    // 3) pack [ref | nei] and bottleneck conv
    pack_cat_kernel<<<(NIMG * 128 * HW) / 256, 256>>>(feat, cat);
    launch_conv_tc(cat, pw_bn, b_bn, bufA, nullptr, 128, 64, 2);

    // 4) four chained DCN stages
    dim3 ggemm(HW / 128, NIMG);
    const int im2colBlocks = (NIMG * 72 * HW) / 256;

    auto dcn_stage = [&](const float* xsrc, const float* feaSrc, int di, float* outBuf) {
        launch_conv_tc(feaSrc, pw_off[di], off_b + di * 64, obuf, nullptr, 64, 64, 2);
        launch_conv_tc(obuf, pw_com[di], com_b + di * 216, om, nullptr, 64, 216, 0);  // no round: feeds im2col math
        dcn_im2col_kernel<<<im2colBlocks, 256>>>(xsrc, om, colb);
        gemm_tc2<<<ggemm, 256>>>(pw_gemm[di], colb, dcn_b + di * 64, outBuf);
    };

    dcn_stage(bufA, bufA, 0, bufT);   // fea = dcn(fea, o0)
    dcn_stage(bufT, bufT, 1, bufA);   // fea = dcn(fea, o1)
    dcn_stage(feat, bufA, 2, bufT);   // fea = dcn(nei, o2)
    dcn_stage(bufT, bufT, 3, bufA);   // aligned = dcn(fea, o3)

    // 5) reconstruction conv (Cout=1, FFMA) straight into d_out, no rounding
    launch_conv_ffma(bufA, w_rec, b_rec, out, nullptr, 64, 1, 0, 0);
}

// round 5
// speedup vs baseline: 4.0483x; 1.4354x over previous
#include <cuda_runtime.h>
#include <math.h>
#include <stdint.h>

#define HH 128
#define WW 128
#define HW 16384
#define NIMG 20
#define CHUNK 4

// ---------------- scratch (device globals; no allocation allowed) ----------------
__device__ float g_bufA[(size_t)NIMG * 64 * HW];
__device__ float g_bufB[(size_t)NIMG * 64 * HW];
__device__ float g_bufT[(size_t)NIMG * 64 * HW];
__device__ float g_off [(size_t)NIMG * 64 * HW];
__device__ float g_om  [(size_t)NIMG * 216 * HW];
__device__ float g_wprep[1327104];   // prepped tf32 fragment-layout weights

// ---------------- helpers ----------------
__device__ __forceinline__ uint32_t smem_u32(const void* p) {
    uint32_t a;
    asm("{ .reg .u64 t; cvta.to.shared.u64 t, %1; cvt.u32.u64 %0, t; }" : "=r"(a) : "l"(p));
    return a;
}
__device__ __forceinline__ float to_tf32(float v) {
    unsigned u; asm("cvt.rna.tf32.f32 %0, %1;" : "=r"(u) : "f"(v));
    return __uint_as_float(u);
}
__device__ __forceinline__ void cp16(uint32_t dst, const void* src, unsigned nbytes) {
    asm volatile("cp.async.cg.shared.global [%0], [%1], 16, %2;"
                 :: "r"(dst), "l"(src), "r"(nbytes) : "memory");
}
__device__ __forceinline__ void cp_commit() {
    asm volatile("cp.async.commit_group;" ::: "memory");
}
__device__ __forceinline__ void cp_wait1() {
    asm volatile("cp.async.wait_group 1;" ::: "memory");
}
__device__ __forceinline__ void cp_wait0() {
    asm volatile("cp.async.wait_group 0;" ::: "memory");
}
__device__ __forceinline__ void mma_tf32(float* c, const float* a, const float* b) {
    asm volatile(
        "mma.sync.aligned.m16n8k8.row.col.f32.tf32.tf32.f32 "
        "{%0,%1,%2,%3}, {%4,%5,%6,%7}, {%8,%9}, {%0,%1,%2,%3};"
        : "+f"(c[0]), "+f"(c[1]), "+f"(c[2]), "+f"(c[3])
        : "r"(__float_as_uint(a[0])), "r"(__float_as_uint(a[1])),
          "r"(__float_as_uint(a[2])), "r"(__float_as_uint(a[3])),
          "r"(__float_as_uint(b[0])), "r"(__float_as_uint(b[1])));
}

// ---------------- weight prep ----------------
// conv dst: [zb][ky][cc16][kx(3)][s(2)][wM(2)][mi(2)][lane(32)][q(4)]  (3072 per (zb,ky,cc16))
__global__ void prep_conv_kernel(const float* __restrict__ w, float* __restrict__ dst,
                                 int Cin, int Cout, int total)
{
    const int gid = blockIdx.x * 256 + threadIdx.x;
    if (gid >= total) return;
    const int q    = gid & 3;
    const int lane = (gid >> 2) & 31;
    const int mi   = (gid >> 7) & 1;
    const int wM   = (gid >> 8) & 1;
    const int s    = (gid >> 9) & 1;
    const int kx   = (gid >> 10) % 3;
    const int t    = gid / 3072;
    const int nci16 = Cin >> 4;
    const int cc   = t % nci16;
    const int t2   = t / nci16;
    const int ky   = t2 % 3;
    const int zb   = t2 / 3;
    const int g    = lane >> 2, t4 = lane & 3;
    const int co   = zb * 64 + wM * 32 + mi * 16 + ((q & 1) << 3) + g;
    const int ci   = cc * 16 + s * 8 + t4 + ((q >> 1) << 2);
    const int k    = ky * 3 + kx;
    float v = (co < Cout) ? w[((size_t)co * Cin + ci) * 9 + k] : 0.f;
    dst[gid] = to_tf32(v);
}

// gemm dst: [chunk(72 = g*9+k)][wM][mi][lane][q]  (512 per chunk), W:[64,576]
__global__ void prep_gemm_kernel(const float* __restrict__ w, float* __restrict__ dst)
{
    const int gid = blockIdx.x * 256 + threadIdx.x;   // 36864 total
    const int frag = gid & 511;
    const int q    = frag & 3;
    const int lane = (frag >> 2) & 31;
    const int mi   = (frag >> 7) & 1;
    const int wM   = frag >> 8;
    const int chunk = gid >> 9;
    const int g = chunk / 9, k = chunk - g * 9;
    const int co = wM * 32 + mi * 16 + ((q & 1) << 3) + (lane >> 2);
    const int ci = (lane & 3) + ((q >> 1) << 2);
    const int kdim = (g * 8 + ci) * 9 + k;
    dst[gid] = to_tf32(w[(size_t)co * 576 + kdim]);
}

// ---------------- tf32 implicit-GEMM 3x3 SAME conv, 16-ci chunks ----------------
// Block 256 thr = 8 warps (2M x 4N). Tile: 64 Cout x 128 px (one row). Chunk = (ky, 16 ci).
__global__ __launch_bounds__(256, 3) void conv3x3_tc2(
    const float* __restrict__ in, const float* __restrict__ wp,
    const float* __restrict__ bias, float* __restrict__ out,
    const float* __restrict__ addsrc, int Cin, int Cout, int flags)
{
    __shared__ __align__(16) float sIn[2][2176];    // [ci(16)][136]: gc=0 at col 4
    __shared__ __align__(16) float sWq[2][3072];    // [kx(3)][s(2)][512]

    const int row  = blockIdx.x;
    const int img  = blockIdx.y;
    const int zb   = blockIdx.z;
    const int coT  = zb << 6;
    const int tid  = threadIdx.x;
    const int warp = tid >> 5;
    const int lane = tid & 31;
    const int g    = lane >> 2, t4 = lane & 3;
    const int wM   = warp & 1,  wN = warp >> 1;
    const int nci16 = Cin >> 4;
    const int nch  = 3 * nci16;
    const int catMode = flags & 4;

    const uint32_t sInB = smem_u32(sIn);
    const uint32_t sWB  = smem_u32(sWq);
    const float* inImg  = in + (size_t)img * (catMode ? 64 : Cin) * HW;
    const float* refImg = catMode ? in + (size_t)((img / 5) * 5 + 2) * 64 * HW : inImg;
    const float* wpL    = wp + (size_t)zb * nch * 3072;

    float acc[2][4][4];
#pragma unroll
    for (int i = 0; i < 2; i++)
#pragma unroll
        for (int j = 0; j < 4; j++)
#pragma unroll
            for (int l = 0; l < 4; l++) acc[i][j][l] = 0.f;

    // zero the two halo columns in both buffers (16 ci x 2 buf x 2 cols)
    if (tid < 64) {
        const int b = tid >> 5, r = tid & 31;
        sIn[b][(r >> 1) * 136 + ((r & 1) ? 132 : 3)] = 0.f;
    }

    auto loadChunk = [&](int c, int buf) {
        const int ky = c / nci16, cc = c - ky * nci16;
        int gr = row + ky - 1;
        const unsigned rs = ((unsigned)gr < HH) ? 16u : 0u;
        if (gr < 0) gr = 0; else if (gr > HH - 1) gr = HH - 1;
        const float* src;
        int ciBase;
        if (catMode) {
            if (cc < 4) { src = refImg; ciBase = cc * 16; }
            else        { src = inImg;  ciBase = (cc - 4) * 16; }
        } else { src = inImg; ciBase = cc * 16; }
        // input: 16 ci x 32 float4 (2 per thread)
#pragma unroll
        for (int i = tid; i < 512; i += 256) {
            const int ci = i >> 5, j = i & 31;
            cp16(sInB + (buf * 2176 + ci * 136 + 4 + 4 * j) * 4,
                 src + (size_t)(ciBase + ci) * HW + gr * WW + 4 * j, rs);
        }
        // weights: 768 float4 contiguous (3 per thread)
        const float* ws = wpL + (size_t)c * 3072;
#pragma unroll
        for (int i = tid; i < 768; i += 256)
            cp16(sWB + (buf * 3072 + 4 * i) * 4, ws + 4 * i, 16);
        cp_commit();
    };

    loadChunk(0, 0);
    for (int c = 0; c < nch; c++) {
        const int buf = c & 1;
        if (c + 1 < nch) { loadChunk(c + 1, buf ^ 1); cp_wait1(); }
        else             { cp_wait0(); }
        __syncthreads();

        const float* sI  = sIn[buf];
        const float* sWb = sWq[buf];
#pragma unroll
        for (int kx = 0; kx < 3; kx++) {
#pragma unroll
            for (int s = 0; s < 2; s++) {
                const float4 a0 = *(const float4*)&sWb[kx * 1024 + s * 512 + wM * 256 + lane * 4];
                const float4 a1 = *(const float4*)&sWb[kx * 1024 + s * 512 + wM * 256 + 128 + lane * 4];
                const int bo = (s * 8 + t4) * 136 + 3 + kx + wN * 32 + g;
#pragma unroll
                for (int ni = 0; ni < 4; ni++) {
                    float b2[2] = { sI[bo + ni * 8], sI[bo + 544 + ni * 8] };
                    mma_tf32(acc[0][ni], (const float*)&a0, b2);
                    mma_tf32(acc[1][ni], (const float*)&a1, b2);
                }
            }
        }
        __syncthreads();
    }

    // epilogue
    const int doRelu  = flags & 1;
    const int doRound = flags & 2;
#pragma unroll
    for (int mi = 0; mi < 2; mi++) {
#pragma unroll
        for (int rr = 0; rr < 2; rr++) {
            const int co = coT + wM * 32 + mi * 16 + rr * 8 + g;
            if (co < Cout) {
                const float bv = bias[co];
                const size_t base = ((size_t)img * Cout + co) * HW + row * WW + wN * 32 + 2 * t4;
#pragma unroll
                for (int ni = 0; ni < 4; ni++) {
                    float v0 = acc[mi][ni][rr * 2 + 0] + bv;
                    float v1 = acc[mi][ni][rr * 2 + 1] + bv;
                    const size_t idx = base + ni * 8;
                    if (addsrc) {
                        float2 r2 = *(const float2*)&addsrc[idx];
                        v0 += r2.x; v1 += r2.y;
                    }
                    if (doRelu) { v0 = fmaxf(v0, 0.f); v1 = fmaxf(v1, 0.f); }
                    if (doRound) { v0 = to_tf32(v0); v1 = to_tf32(v1); }
                    *(float2*)&out[idx] = make_float2(v0, v1);
                }
            }
        }
    }
}

// ---------------- fused deformable-im2col + GEMM (Cout=64, K=576) ----------------
// Block 256. Tile: 64 co x 128 px (one image row). K chunk = one (g,k): 8 channels.
// Gathers for chunk c+1 issued before chunk c's MMAs; combined at STS.
__global__ __launch_bounds__(256, 3) void dcn_fused_kernel(
    const float* __restrict__ wp,   // [72][512] prepped
    const float* __restrict__ x,    // [img][64][HW] sampled input
    const float* __restrict__ om,   // [img][216][HW] offset-mask conv output
    const float* __restrict__ bias,
    float* __restrict__ out)        // [img][64][HW]
{
    __shared__ __align__(16) float sB[2][1088];   // [ci(8)][136]
    __shared__ __align__(16) float sW[2][512];

    const int pxb  = blockIdx.x << 7;
    const int img  = blockIdx.y;
    const int tid  = threadIdx.x;
    const int warp = tid >> 5;
    const int lane = tid & 31;
    const int g_   = lane >> 2, t4 = lane & 3;
    const int wM   = warp & 1,  wN = warp >> 1;
    const int pxl  = tid & 127;
    const int half = tid >> 7;          // ci sub-block 0..3 / 4..7
    const int h    = pxb >> 7;          // whole block shares one image row
    const int w    = pxl;

    const uint32_t sBB = smem_u32(sB);
    const uint32_t sWB = smem_u32(sW);
    const float* omj = om + (size_t)img * 216 * HW + pxb + pxl;
    const float* xg  = x + (size_t)img * 64 * HW;

    float acc[2][4][4];
#pragma unroll
    for (int i = 0; i < 2; i++)
#pragma unroll
        for (int j = 0; j < 4; j++)
#pragma unroll
            for (int l = 0; l < 4; l++) acc[i][j][l] = 0.f;

    float rv[16];    // raw gathered corners
    float fw[4];     // bilinear*mask weights

    auto gatherIssue = [&](int c) {
        const int gg = c / 9, k = c - gg * 9;
        const float dy = omj[(size_t)c * HW];
        const float dx = omj[(size_t)(72 + c) * HW];
        float m        = omj[(size_t)(144 + c) * HW];
        m = 1.f / (1.f + expf(-m));
        const float py  = (float)(h + k / 3 - 1) + dy;
        const float pxf = (float)(w + k % 3 - 1) + dx;
        const float y0f = floorf(py), x0f = floorf(pxf);
        const float wy = py - y0f, wx = pxf - x0f;
        const int y0 = (int)y0f, x0 = (int)x0f;
        const int y1 = y0 + 1,   x1 = x0 + 1;
        const bool vy0 = (y0 >= 0) & (y0 < HH), vy1 = (y1 >= 0) & (y1 < HH);
        const bool vx0 = (x0 >= 0) & (x0 < WW), vx1 = (x1 >= 0) & (x1 < WW);
        const int cy0 = min(max(y0, 0), HH - 1), cy1 = min(max(y1, 0), HH - 1);
        const int cx0 = min(max(x0, 0), WW - 1), cx1 = min(max(x1, 0), WW - 1);
        fw[0] = (1.f - wy) * (1.f - wx) * m * ((vy0 && vx0) ? 1.f : 0.f);
        fw[1] = (1.f - wy) * wx         * m * ((vy0 && vx1) ? 1.f : 0.f);
        fw[2] = wy * (1.f - wx)         * m * ((vy1 && vx0) ? 1.f : 0.f);
        fw[3] = wy * wx                 * m * ((vy1 && vx1) ? 1.f : 0.f);
        const int i00 = cy0 * WW + cx0, i01 = cy0 * WW + cx1;
        const int i10 = cy1 * WW + cx0, i11 = cy1 * WW + cx1;
        const float* b = xg + (size_t)(gg * 8 + half * 4) * HW;
#pragma unroll
        for (int cc = 0; cc < 4; cc++) {
            const float* xc = b + (size_t)cc * HW;
            rv[cc * 4 + 0] = xc[i00];
            rv[cc * 4 + 1] = xc[i01];
            rv[cc * 4 + 2] = xc[i10];
            rv[cc * 4 + 3] = xc[i11];
        }
    };
    auto stageW = [&](int c, int buf) {
        if (tid < 128)
            cp16(sWB + (buf * 512 + 4 * tid) * 4, wp + (size_t)c * 512 + 4 * tid, 16);
        cp_commit();
    };
    auto stsB = [&](int buf) {
#pragma unroll
        for (int cc = 0; cc < 4; cc++) {
            const float v = fw[0] * rv[cc * 4] + fw[1] * rv[cc * 4 + 1]
                          + fw[2] * rv[cc * 4 + 2] + fw[3] * rv[cc * 4 + 3];
            sB[buf][(half * 4 + cc) * 136 + pxl] = to_tf32(v);
        }
    };

    stageW(0, 0);
    gatherIssue(0);
    stsB(0);
    cp_wait0();
    __syncthreads();

    for (int c = 0; c < 72; c++) {
        const int buf = c & 1;
        if (c < 71) { stageW(c + 1, buf ^ 1); gatherIssue(c + 1); }
        // MMA on current chunk
        const float* sBb = sB[buf];
        const float* sWb = sW[buf];
        const float4 a0 = *(const float4*)&sWb[wM * 256 + lane * 4];
        const float4 a1 = *(const float4*)&sWb[wM * 256 + 128 + lane * 4];
        const int bo = t4 * 136 + wN * 32 + g_;
#pragma unroll
        for (int ni = 0; ni < 4; ni++) {
            float b2[2] = { sBb[bo + ni * 8], sBb[bo + 544 + ni * 8] };
            mma_tf32(acc[0][ni], (const float*)&a0, b2);
            mma_tf32(acc[1][ni], (const float*)&a1, b2);
        }
        if (c < 71) { stsB(buf ^ 1); cp_wait0(); }
        __syncthreads();
    }

#pragma unroll
    for (int mi = 0; mi < 2; mi++) {
#pragma unroll
        for (int rr = 0; rr < 2; rr++) {
            const int co = wM * 32 + mi * 16 + rr * 8 + g_;
            const float bv = bias[co];
            const size_t base = ((size_t)img * 64 + co) * HW + pxb + wN * 32 + 2 * t4;
#pragma unroll
            for (int ni = 0; ni < 4; ni++) {
                float v0 = to_tf32(acc[mi][ni][rr * 2 + 0] + bv);
                float v1 = to_tf32(acc[mi][ni][rr * 2 + 1] + bv);
                *(float2*)&out[base + ni * 8] = make_float2(v0, v1);
            }
        }
    }
}

// ---------------- FFMA 3x3 conv (Cin=1 / Cout=1 cases) ----------------
__global__ __launch_bounds__(256, 2) void conv3x3_kernel(
    const float* __restrict__ in, const float* __restrict__ wt,
    const float* __restrict__ bias, float* __restrict__ out,
    const float* __restrict__ addsrc,
    int Cin, int Cout, int doRelu, int doRound)
{
    __shared__ __align__(16) float sIn[CHUNK][18][80];
    __shared__ __align__(16) float sW[CHUNK][9][16];

    const int tw  = blockIdx.x & 1;
    const int th  = blockIdx.x >> 1;
    const int img = blockIdx.y;
    const int cob = blockIdx.z * 16;
    const int tid = threadIdx.x;
    const int tx  = tid & 15;
    const int ty  = tid >> 4;

    float acc[4][16];
#pragma unroll
    for (int p = 0; p < 4; p++)
#pragma unroll
        for (int c = 0; c < 16; c++) acc[p][c] = 0.f;

    const int nch = (Cin + CHUNK - 1) / CHUNK;
    for (int cc = 0; cc < nch; cc++) {
        const int cin0 = cc * CHUNK;
        for (int idx = tid; idx < CHUNK * 18 * 66; idx += 256) {
            int ci  = idx / (18 * 66);
            int rem = idx - ci * (18 * 66);
            int r = rem / 66, c = rem - r * 66;
            int gr = th * 16 + r - 1;
            int gc = tw * 64 + c - 1;
            int cin = cin0 + ci;
            float v = 0.f;
            if (cin < Cin && gr >= 0 && gr < HH && gc >= 0 && gc < WW)
                v = in[((size_t)img * Cin + cin) * HW + gr * WW + gc];
            sIn[ci][r][c] = v;
        }
        for (int idx = tid; idx < CHUNK * 9 * 16; idx += 256) {
            int ci  = idx / 144;
            int rem = idx - ci * 144;
            int k = rem >> 4, co = rem & 15;
            int cin = cin0 + ci;
            float v = 0.f;
            if (cin < Cin && (cob + co) < Cout)
                v = wt[((size_t)(cob + co) * Cin + cin) * 9 + k];
            sW[ci][k][co] = v;
        }
        __syncthreads();

        for (int ci = 0; ci < CHUNK; ci++) {
#pragma unroll
            for (int k = 0; k < 9; k++) {
                const int ky = k / 3, kx = k - ky * 3;
                const float4 w0 = *(const float4*)&sW[ci][k][0];
                const float4 w1 = *(const float4*)&sW[ci][k][4];
                const float4 w2 = *(const float4*)&sW[ci][k][8];
                const float4 w3 = *(const float4*)&sW[ci][k][12];
                const float wv[16] = {w0.x, w0.y, w0.z, w0.w, w1.x, w1.y, w1.z, w1.w,
                                      w2.x, w2.y, w2.z, w2.w, w3.x, w3.y, w3.z, w3.w};
#pragma unroll
                for (int p = 0; p < 4; p++) {
                    const float xv = sIn[ci][ty + ky][tx + 16 * p + kx];
#pragma unroll
                    for (int co = 0; co < 16; co++)
                        acc[p][co] = fmaf(xv, wv[co], acc[p][co]);
                }
            }
        }
        __syncthreads();
    }

    const int row = th * 16 + ty;
    const int colb2 = tw * 64 + tx;
#pragma unroll
    for (int co = 0; co < 16; co++) {
        const int oc = cob + co;
        if (oc < Cout) {
            const float b = bias[oc];
#pragma unroll
            for (int p = 0; p < 4; p++) {
                const size_t idx = ((size_t)img * Cout + oc) * HW + row * WW + colb2 + 16 * p;
                float v = acc[p][co] + b;
                if (addsrc) v += addsrc[idx];
                if (doRelu) v = fmaxf(v, 0.f);
                if (doRound) v = to_tf32(v);
                out[idx] = v;
            }
        }
    }
}

// ---------------- host launcher ----------------
static inline void launch_conv_ffma(const float* in, const float* w, const float* b,
                                    float* out, const float* add,
                                    int Cin, int Cout, int relu, int roundOut)
{
    dim3 grid(16, NIMG, (Cout + 15) / 16);
    conv3x3_kernel<<<grid, 256>>>(in, w, b, out, add, Cin, Cout, relu, roundOut);
}

static inline void launch_conv_tc(const float* in, const float* wp, const float* b,
                                  float* out, const float* add,
                                  int Cin, int Cout, int flags)
{
    dim3 grid(HH, NIMG, (Cout + 63) / 64);
    conv3x3_tc2<<<grid, 256>>>(in, wp, b, out, add, Cin, Cout, flags);
}

extern "C" void kernel_launch(void* const* d_in, const int* in_sizes, int n_in,
                              void* d_out, int out_size)
{
    const float* x       = (const float*)d_in[0];
    const float* w_init  = (const float*)d_in[1];
    const float* b_init  = (const float*)d_in[2];
    const float* res_w1  = (const float*)d_in[3];
    const float* res_b1  = (const float*)d_in[4];
    const float* res_w2  = (const float*)d_in[5];
    const float* res_b2  = (const float*)d_in[6];
    const float* w_bn    = (const float*)d_in[7];
    const float* b_bn    = (const float*)d_in[8];
    const float* off_w   = (const float*)d_in[9];
    const float* off_b   = (const float*)d_in[10];
    const float* com_w   = (const float*)d_in[11];
    const float* com_b   = (const float*)d_in[12];
    const float* dcn_w   = (const float*)d_in[13];
    const float* dcn_b   = (const float*)d_in[14];
    const float* w_rec   = (const float*)d_in[15];
    const float* b_rec   = (const float*)d_in[16];
    float* out = (float*)d_out;

    float *bufA, *bufB, *bufT, *obuf, *om, *wprep;
    cudaGetSymbolAddress((void**)&bufA, g_bufA);
    cudaGetSymbolAddress((void**)&bufB, g_bufB);
    cudaGetSymbolAddress((void**)&bufT, g_bufT);
    cudaGetSymbolAddress((void**)&obuf, g_off);
    cudaGetSymbolAddress((void**)&om,   g_om);
    cudaGetSymbolAddress((void**)&wprep, g_wprep);

    // ---- weight prep (tiny launches) ----
    size_t off = 0;
    auto prepConv = [&](const float* w, int Cin, int Cout) -> const float* {
        float* d = wprep + off;
        const int zb = (Cout + 63) / 64;
        const int tot = zb * 3 * (Cin / 16) * 3072;
        prep_conv_kernel<<<(tot + 255) / 256, 256>>>(w, d, Cin, Cout, tot);
        off += (size_t)tot;
        return d;
    };
    auto prepGemm = [&](const float* w) -> const float* {
        float* d = wprep + off;
        prep_gemm_kernel<<<144, 256>>>(w, d);
        off += 36864;
        return d;
    };

    const float* pw_r1[5]; const float* pw_r2[5];
    for (int i = 0; i < 5; i++) pw_r1[i] = prepConv(res_w1 + (size_t)i * 36864, 64, 64);
    for (int i = 0; i < 5; i++) pw_r2[i] = prepConv(res_w2 + (size_t)i * 36864, 64, 64);
    const float* pw_bn = prepConv(w_bn, 128, 64);
    const float* pw_off[4]; const float* pw_com[4]; const float* pw_gemm[4];
    for (int d = 0; d < 4; d++) pw_off[d]  = prepConv(off_w + (size_t)d * 36864, 64, 64);
    for (int d = 0; d < 4; d++) pw_com[d]  = prepConv(com_w + (size_t)d * 216 * 64 * 9, 64, 216);
    for (int d = 0; d < 4; d++) pw_gemm[d] = prepGemm(dcn_w + (size_t)d * 36864);

    // ---- network ----
    // 1) init conv + relu (Cin=1, FFMA), round output to tf32
    launch_conv_ffma(x, w_init, b_init, bufA, nullptr, 1, 64, 1, 1);

    // 2) 5 residual blocks
    float* cur = bufA;
    float* nxt = bufB;
    for (int i = 0; i < 5; i++) {
        launch_conv_tc(cur, pw_r1[i], res_b1 + i * 64, bufT, nullptr, 64, 64, 1 | 2);
        launch_conv_tc(bufT, pw_r2[i], res_b2 + i * 64, nxt, cur, 64, 64, 2);
        float* t = cur; cur = nxt; nxt = t;
    }
    float* feat = cur;

    // 3) bottleneck conv directly over [ref | nei] (cat folded into loads)
    launch_conv_tc(feat, pw_bn, b_bn, bufA, nullptr, 128, 64, 2 | 4);

    // 4) four chained DCN stages (offset conv -> offset-mask conv -> fused im2col+GEMM)
    dim3 ggemm(HW / 128, NIMG);
    auto dcn_stage = [&](const float* xsrc, const float* feaSrc, int di, float* outBuf) {
        launch_conv_tc(feaSrc, pw_off[di], off_b + di * 64, obuf, nullptr, 64, 64, 2);
        launch_conv_tc(obuf, pw_com[di], com_b + di * 216, om, nullptr, 64, 216, 0);  // raw: feeds im2col math
        dcn_fused_kernel<<<ggemm, 256>>>(pw_gemm[di], xsrc, om, dcn_b + di * 64, outBuf);
    };

    dcn_stage(bufA, bufA, 0, bufT);   // fea = dcn(fea, o0)
    dcn_stage(bufT, bufT, 1, bufA);   // fea = dcn(fea, o1)
    dcn_stage(feat, bufA, 2, bufT);   // fea = dcn(nei, o2)
    dcn_stage(bufT, bufT, 3, bufA);   // aligned = dcn(fea, o3)

    // 5) reconstruction conv (Cout=1, FFMA) straight into d_out
    launch_conv_ffma(bufA, w_rec, b_rec, out, nullptr, 64, 1, 0, 0);
}